// round 3
// baseline (speedup 1.0000x reference)
#include <cuda_runtime.h>
#include <cuda_fp16.h>
#include <cstdint>

// ---------------------------------------------------------------------------
// BitLinear: out = x @ ternary(w)^T + bias
// x: [8192, 4096] fp32, w: [4096, 4096] fp32, bias: [4096] fp32, out fp32.
//
// tcgen05 is unavailable (harness compiles via compute_103 PTX; 'a'-features
// rejected by ptxas). Use classic mma.sync m16n8k16 fp16->fp32 with a 3-stage
// cp.async pipeline. w quantized to exact ternary fp16, x converted to fp16
// (rel err ~3e-4 after K=4096 accumulation, under the 1e-3 gate).
// ---------------------------------------------------------------------------

#define MDIM 8192
#define NDIM 4096
#define KDIM 4096

#define BM 128
#define BN 128
#define BK 64
#define STAGES 3
#define KT (KDIM / BK)   // 64

// Scratch (device globals: allocation-free per harness rules)
__device__ double g_partials[1024];
__device__ float  g_gamma_inv;
__device__ __half g_xq[(size_t)MDIM * KDIM];   // 64 MB
__device__ __half g_wq[(size_t)NDIM * KDIM];   // 32 MB

// ---------------------------------------------------------------------------
// Helpers
// ---------------------------------------------------------------------------
static __device__ __forceinline__ uint32_t smem_u32(const void* p) {
    uint32_t a;
    asm("{ .reg .u64 t; cvta.to.shared.u64 t, %1; cvt.u32.u64 %0, t; }"
        : "=r"(a) : "l"(p));
    return a;
}

static __device__ __forceinline__ void cp_async16(uint32_t s, const void* g) {
    asm volatile("cp.async.cg.shared.global [%0], [%1], 16;" :: "r"(s), "l"(g));
}

// SW128-style xor swizzle on byte offsets within 128B rows: bits[6:4] ^= bits[9:7]
#define SWZ(o) ((o) ^ (((o) >> 3) & 0x70))

#define LDSM_X4(r0, r1, r2, r3, addr)                                          \
    asm volatile("ldmatrix.sync.aligned.m8n8.x4.shared.b16 {%0,%1,%2,%3}, [%4];"\
                 : "=r"(r0), "=r"(r1), "=r"(r2), "=r"(r3) : "r"(addr))

#define LDSM_X2(r0, r1, addr)                                                  \
    asm volatile("ldmatrix.sync.aligned.m8n8.x2.shared.b16 {%0,%1}, [%2];"     \
                 : "=r"(r0), "=r"(r1) : "r"(addr))

#define MMA_16816(c, a, b)                                                     \
    asm volatile(                                                              \
        "mma.sync.aligned.m16n8k16.row.col.f32.f16.f16.f32 "                   \
        "{%0,%1,%2,%3}, {%4,%5,%6,%7}, {%8,%9}, {%0,%1,%2,%3};"                \
        : "+f"((c)[0]), "+f"((c)[1]), "+f"((c)[2]), "+f"((c)[3])               \
        : "r"((a)[0]), "r"((a)[1]), "r"((a)[2]), "r"((a)[3]),                  \
          "r"((b)[0]), "r"((b)[1]))

// ---------------------------------------------------------------------------
// Pre-pass kernels
// ---------------------------------------------------------------------------
__global__ void absum_partial_kernel(const float* __restrict__ w) {
    __shared__ double sred[256];
    const float4* w4 = reinterpret_cast<const float4*>(w);
    const int n4 = (NDIM * KDIM) / 4;
    double s = 0.0;
    for (int i = blockIdx.x * blockDim.x + threadIdx.x; i < n4;
         i += gridDim.x * blockDim.x) {
        float4 v = w4[i];
        s += (double)(fabsf(v.x) + fabsf(v.y) + fabsf(v.z) + fabsf(v.w));
    }
    sred[threadIdx.x] = s;
    __syncthreads();
    for (int o = 128; o > 0; o >>= 1) {
        if (threadIdx.x < o) sred[threadIdx.x] += sred[threadIdx.x + o];
        __syncthreads();
    }
    if (threadIdx.x == 0) g_partials[blockIdx.x] = sred[0];
}

__global__ void absum_final_kernel() {
    __shared__ double sred[256];
    double s = 0.0;
    for (int i = threadIdx.x; i < 1024; i += 256) s += g_partials[i];
    sred[threadIdx.x] = s;
    __syncthreads();
    for (int o = 128; o > 0; o >>= 1) {
        if (threadIdx.x < o) sred[threadIdx.x] += sred[threadIdx.x + o];
        __syncthreads();
    }
    if (threadIdx.x == 0) {
        double g = sred[0] / (double)((size_t)NDIM * KDIM);
        if (g < 1e-8) g = 1e-8;
        g_gamma_inv = (float)(1.0 / g);
    }
}

__global__ void quant_w_kernel(const float* __restrict__ w) {
    const float ginv = g_gamma_inv;
    const float4* w4 = reinterpret_cast<const float4*>(w);
    uint2* q = reinterpret_cast<uint2*>(g_wq);
    const int n4 = (NDIM * KDIM) / 4;
    for (int i = blockIdx.x * blockDim.x + threadIdx.x; i < n4;
         i += gridDim.x * blockDim.x) {
        float4 v = w4[i];
        float a = fminf(1.f, fmaxf(-1.f, rintf(v.x * ginv)));
        float b = fminf(1.f, fmaxf(-1.f, rintf(v.y * ginv)));
        float c = fminf(1.f, fmaxf(-1.f, rintf(v.z * ginv)));
        float d = fminf(1.f, fmaxf(-1.f, rintf(v.w * ginv)));
        __half2 h0 = __floats2half2_rn(a, b);
        __half2 h1 = __floats2half2_rn(c, d);
        uint2 u;
        u.x = *reinterpret_cast<unsigned*>(&h0);
        u.y = *reinterpret_cast<unsigned*>(&h1);
        q[i] = u;
    }
}

__global__ void conv_x_kernel(const float* __restrict__ x) {
    const float4* x4 = reinterpret_cast<const float4*>(x);
    uint2* q = reinterpret_cast<uint2*>(g_xq);
    const int n4 = (MDIM * KDIM) / 4;
    for (int i = blockIdx.x * blockDim.x + threadIdx.x; i < n4;
         i += gridDim.x * blockDim.x) {
        float4 v = x4[i];
        __half2 h0 = __floats2half2_rn(v.x, v.y);
        __half2 h1 = __floats2half2_rn(v.z, v.w);
        uint2 u;
        u.x = *reinterpret_cast<unsigned*>(&h0);
        u.y = *reinterpret_cast<unsigned*>(&h1);
        q[i] = u;
    }
}

// ---------------------------------------------------------------------------
// GEMM: 128x128 CTA tile, BK=64, 3-stage cp.async, mma.sync m16n8k16.
// SMEM per stage: A 128x64 fp16 (16KB, 128B rows, SWZ), B 128x64 fp16 (16KB).
// A stages at [0, 48K), B stages at [48K, 96K).
// ---------------------------------------------------------------------------
static constexpr int STAGE_BYTES = BM * BK * 2;           // 16384
static constexpr int SMEM_BYTES  = 2 * STAGES * STAGE_BYTES;  // 98304

__global__ __launch_bounds__(256, 2)
void bitlinear_gemm_kernel(const float* __restrict__ bias, float* __restrict__ out) {
    extern __shared__ __align__(128) char smem_raw[];
    const uint32_t sbase = smem_u32(smem_raw);
    const uint32_t sBb   = sbase + STAGES * STAGE_BYTES;

    const int tid    = threadIdx.x;
    const int wid    = tid >> 5;
    const int lane   = tid & 31;
    const int warp_m = wid & 1;        // 0..1 -> 64 rows each
    const int warp_n = wid >> 1;       // 0..3 -> 32 cols each
    const int m0 = blockIdx.y * BM;
    const int n0 = blockIdx.x * BN;

    const __half* Ag = g_xq + (size_t)m0 * KDIM;
    const __half* Bg = g_wq + (size_t)n0 * KDIM;

    // Per-thread load pattern: 1024 16B-chunks per tile / 256 threads = 4 each.
    // chunk c: row = c>>3 (128B rows), kc = c&7.
    const int lrow0 = tid >> 3;        // rows tid>>3 + {0,32,64,96}
    const int lkc   = tid & 7;

    float acc[4][4][4];
    #pragma unroll
    for (int i = 0; i < 4; i++)
        #pragma unroll
        for (int j = 0; j < 4; j++)
            #pragma unroll
            for (int r = 0; r < 4; r++) acc[i][j][r] = 0.f;

    auto load_stage = [&](int kt) {
        const int s = kt % STAGES;
        const uint32_t sA = sbase + s * STAGE_BYTES;
        const uint32_t sB = sBb   + s * STAGE_BYTES;
        const __half* Akt = Ag + kt * BK;
        const __half* Bkt = Bg + kt * BK;
        #pragma unroll
        for (int i = 0; i < 4; i++) {
            const int r = lrow0 + i * 32;
            const uint32_t d = SWZ((uint32_t)(r * 128 + lkc * 16));
            cp_async16(sA + d, Akt + (size_t)r * KDIM + lkc * 8);
            cp_async16(sB + d, Bkt + (size_t)r * KDIM + lkc * 8);
        }
    };

    // Prologue: stages 0, 1
    load_stage(0);
    asm volatile("cp.async.commit_group;" ::: "memory");
    load_stage(1);
    asm volatile("cp.async.commit_group;" ::: "memory");

    const int a_row  = warp_m * 64 + (lane & 15);
    const int a_cchk = (lane >> 4);          // 0/1
    const int b_row  = warp_n * 32 + (lane & 7);
    const int b_cchk = (lane >> 3) & 1;      // 0/1

    for (int kt = 0; kt < KT; ++kt) {
        asm volatile("cp.async.wait_group 1;" ::: "memory");
        __syncthreads();

        const int ktn = kt + (STAGES - 1);
        if (ktn < KT) load_stage(ktn);
        asm volatile("cp.async.commit_group;" ::: "memory");

        const int s = kt % STAGES;
        const uint32_t sA = sbase + s * STAGE_BYTES;
        const uint32_t sB = sBb   + s * STAGE_BYTES;

        #pragma unroll
        for (int kk = 0; kk < 4; kk++) {
            uint32_t a[4][4];
            #pragma unroll
            for (int i = 0; i < 4; i++) {
                const uint32_t off = (uint32_t)((a_row + i * 16) * 128
                                                + kk * 32 + a_cchk * 16);
                LDSM_X4(a[i][0], a[i][1], a[i][2], a[i][3], sA + SWZ(off));
            }
            uint32_t b[4][2];
            #pragma unroll
            for (int j = 0; j < 4; j++) {
                const uint32_t off = (uint32_t)((b_row + j * 8) * 128
                                                + kk * 32 + b_cchk * 16);
                LDSM_X2(b[j][0], b[j][1], sB + SWZ(off));
            }
            #pragma unroll
            for (int i = 0; i < 4; i++)
                #pragma unroll
                for (int j = 0; j < 4; j++)
                    MMA_16816(acc[i][j], a[i], b[j]);
        }
    }

    // Epilogue: C frag m16n8: c0 @(r, c), c1 @(r, c+1), c2/c3 @(r+8, c/c+1)
    // where r = lane>>2, c = (lane&3)*2.
    const int er = lane >> 2;
    const int ec = (lane & 3) * 2;
    float bb[4][2];
    #pragma unroll
    for (int j = 0; j < 4; j++) {
        const int col = n0 + warp_n * 32 + j * 8 + ec;
        bb[j][0] = __ldg(bias + col);
        bb[j][1] = __ldg(bias + col + 1);
    }
    #pragma unroll
    for (int i = 0; i < 4; i++) {
        const int row = m0 + warp_m * 64 + i * 16 + er;
        #pragma unroll
        for (int j = 0; j < 4; j++) {
            const int col = n0 + warp_n * 32 + j * 8 + ec;
            float2 v0 = make_float2(acc[i][j][0] + bb[j][0],
                                    acc[i][j][1] + bb[j][1]);
            float2 v1 = make_float2(acc[i][j][2] + bb[j][0],
                                    acc[i][j][3] + bb[j][1]);
            *reinterpret_cast<float2*>(out + (size_t)row * NDIM + col)       = v0;
            *reinterpret_cast<float2*>(out + (size_t)(row + 8) * NDIM + col) = v1;
        }
    }
}

// ---------------------------------------------------------------------------
// Launch
// ---------------------------------------------------------------------------
extern "C" void kernel_launch(void* const* d_in, const int* in_sizes, int n_in,
                              void* d_out, int out_size) {
    const float* x    = (const float*)d_in[0];   // [4,2048,4096]
    const float* w    = (const float*)d_in[1];   // [4096,4096]
    const float* bias = (const float*)d_in[2];   // [4096]
    float* out = (float*)d_out;                  // [4,2048,4096]

    absum_partial_kernel<<<1024, 256>>>(w);
    absum_final_kernel<<<1, 256>>>();
    quant_w_kernel<<<2048, 256>>>(w);
    conv_x_kernel<<<4096, 256>>>(x);

    cudaFuncSetAttribute(bitlinear_gemm_kernel,
                         cudaFuncAttributeMaxDynamicSharedMemorySize, SMEM_BYTES);
    bitlinear_gemm_kernel<<<dim3(NDIM / BN, MDIM / BM), 256, SMEM_BYTES>>>(bias, out);
}